// round 4
// baseline (speedup 1.0000x reference)
#include <cuda_runtime.h>
#include <math.h>

#define B_SZ      4096
#define DIM       128
#define HIST      50
#define TOPN      4
#define PROTO     1024
#define ITEM_NUM  100000
#define KTOT      1152   // 384 text + 768 visual
#define NPART     3      // K split into 3 parts of 384
#define KPART     384

typedef unsigned long long u64;

// ---------------- f32x2 helpers ----------------
__device__ __forceinline__ void ffma2(u64& d, u64 a, u64 b) {
    asm("fma.rn.f32x2 %0, %1, %2, %0;" : "+l"(d) : "l"(a), "l"(b));
}
__device__ __forceinline__ u64 pk2(float x) {
    u64 r; asm("mov.b64 %0, {%1, %1};" : "=l"(r) : "r"(__float_as_uint(x))); return r;
}
__device__ __forceinline__ float2 up2(u64 v) {
    float2 f; asm("mov.b64 {%0, %1}, %2;" : "=f"(f.x), "=f"(f.y) : "l"(v)); return f;
}

// ---------------- scratch ----------------
__device__ float g_Wc[KTOT * DIM];          // [k][d] combined (Wt|Wv)
__device__ float g_W1T[256 * DIM];          // [k][d]
__device__ float g_cbias[DIM];
__device__ float g_huf[B_SZ * DIM];         // h_u_hat = h_u + p_d
__device__ float g_part[NPART][B_SZ * DIM]; // e_i partial sums
__device__ float g_f1[B_SZ * DIM];
__device__ float g_f2[B_SZ * 64];
__device__ float g_p1s[256 * 128];
__device__ float g_p1q[256 * 128];
__device__ float g_p2s[256 * 64];
__device__ float g_p2q[256 * 64];
__device__ float g_effW2T[128 * 64];
__device__ float g_effb2[64];
__device__ float g_effWp[64];
__device__ float g_effbp;

// ---------------- prep: transposes + cbias (merged) ----------------
__global__ void k_prep(const float* __restrict__ Wt, const float* __restrict__ Wv,
                       const float* __restrict__ W1,
                       const float* __restrict__ bt, const float* __restrict__ bv) {
    int b = blockIdx.x;
    if (b < 576) {
        int i = b * 256 + threadIdx.x;
        int k = i >> 7, d = i & 127;
        g_Wc[i] = (k < 384) ? Wt[d * 384 + k] : Wv[d * 768 + (k - 384)];
    } else if (b < 704) {
        int i = (b - 576) * 256 + threadIdx.x;
        int k = i >> 7, d = i & 127;
        g_W1T[i] = W1[d * 256 + k];
    } else {
        int d = b - 704;
        int tid = threadIdx.x;
        float s = 0.f;
        for (int k = tid; k < KTOT; k += 256) {
            float w = (k < 384) ? Wt[d * 384 + k] : Wv[d * 768 + (k - 384)];
            float bb = (k < 384) ? bt[k] : bv[k - 384];
            s = fmaf(w, bb, s);
        }
        __shared__ float red[256];
        red[tid] = s;
        __syncthreads();
        for (int o = 128; o > 0; o >>= 1) {
            if (tid < o) red[tid] += red[tid + o];
            __syncthreads();
        }
        if (tid == 0) g_cbias[d] = red[0];
    }
}

// ================= fused main: blocks [0,256) = h_u, [256,1024) = e_i =================
// 512 threads (16 warps), warp = 1 batch row, lane = 4 dims
__global__ void __launch_bounds__(512) k_main(
                     const int* __restrict__ nodes_u, const int* __restrict__ nodes_d,
                     const int* __restrict__ inter_items, const int* __restrict__ top_n,
                     const float* __restrict__ proto,
                     const float* __restrict__ user_prompt,
                     const float* __restrict__ domain_prompt,
                     const int* __restrict__ nodes_v,
                     const float* __restrict__ pre_text,
                     const float* __restrict__ pre_visual,
                     const float* __restrict__ item_prompt,
                     float* __restrict__ out_pu, float* __restrict__ out_hu,
                     float* __restrict__ out_pd) {
    __shared__ __align__(16) union {
        struct {
            unsigned mask[16][32];
            unsigned sfm[8][PROTO];   // packed pair masks
            float    invc[16];
        } hu;
        struct {
            float sA[16 * KPART];     // 24 KB
            int   item[16];
        } ei;
    } sm;

    int tid = threadIdx.x;
    int warp = tid >> 5, lane = tid & 31;

    if (blockIdx.x < 256) {
        // ---------------- h_u path ----------------
        int row0 = blockIdx.x * 16;

        for (int i = tid; i < 16 * 32; i += 512) ((unsigned*)sm.hu.mask)[i] = 0u;
        __syncthreads();

        for (int t = tid; t < 6400; t += 512) {
            int r = t / 400;
            int e = t - r * 400;
            int slot = e >> 3;
            int w = e & 7;
            int half = w >> 2;
            int j = w & 3;
            int item = inter_items[(row0 + r) * HIST + slot];
            int p = top_n[(item + half * ITEM_NUM) * TOPN + j];
            atomicOr(&sm.hu.mask[r][p >> 5], 1u << (p & 31));
        }
        __syncthreads();

        for (int i = tid; i < 8 * PROTO; i += 512) {
            int pr = i >> 10, p = i & (PROTO - 1);
            unsigned b0 = (sm.hu.mask[2 * pr][p >> 5] >> (p & 31)) & 1u;
            unsigned b1 = (sm.hu.mask[2 * pr + 1][p >> 5] >> (p & 31)) & 1u;
            sm.hu.sfm[pr][p] = (b0 ? 0x3F80u : 0u) | (b1 ? 0x3F800000u : 0u);
        }
        if (tid < 16) {
            int c = 0;
            #pragma unroll
            for (int w = 0; w < 32; ++w) c += __popc(sm.hu.mask[tid][w]);
            sm.hu.invc[tid] = 1.0f / (float)c;
        }
        __syncthreads();

        // warp = 1 row; extract this row's half of the packed pair word
        int pair = warp >> 1;
        int half = warp & 1;
        const unsigned* fm = sm.hu.sfm[pair];
        const float* pbase = proto + 4 * lane;

        u64 aa = 0, ab = 0;
        #pragma unroll 8
        for (int p = 0; p < PROTO; ++p) {
            ulonglong2 w2 = *(const ulonglong2*)(pbase + p * DIM);
            unsigned u = fm[p];
            unsigned bits = half ? (u & 0xFFFF0000u) : (u << 16);
            u64 m = pk2(__uint_as_float(bits));
            ffma2(aa, m, w2.x);
            ffma2(ab, m, w2.y);
        }

        int row = row0 + warp;
        float ic = sm.hu.invc[warp];
        float2 fa = up2(aa), fb = up2(ab);
        float4 hu;
        hu.x = fa.x * ic; hu.y = fa.y * ic; hu.z = fb.x * ic; hu.w = fb.y * ic;
        int dn = nodes_d[row];
        int un = nodes_u[row];
        float4 pd = *(const float4*)&domain_prompt[dn * DIM + 4 * lane];
        float4 pu = *(const float4*)&user_prompt[(long)un * DIM + 4 * lane];
        *(float4*)&out_hu[(long)row * DIM + 4 * lane] = hu;
        *(float4*)&out_pd[(long)row * DIM + 4 * lane] = pd;
        *(float4*)&out_pu[(long)row * DIM + 4 * lane] = pu;
        float4 f;
        f.x = hu.x + pd.x; f.y = hu.y + pd.y; f.z = hu.z + pd.z; f.w = hu.w + pd.w;
        *(float4*)&g_huf[row * DIM + 4 * lane] = f;
    } else {
        // ---------------- e_i split-K path ----------------
        int idx = blockIdx.x - 256;
        int part = idx >> 8;            // 0..2
        int row0 = (idx & 255) * 16;

        if (tid < 16) sm.ei.item[tid] = nodes_v[row0 + tid];
        __syncthreads();

        // stage 16 x 384 activations: 1536 float4 over 512 threads
        #pragma unroll
        for (int j = 0; j < 3; ++j) {
            int f4 = tid + j * 512;
            int row = f4 / 96, c4 = f4 % 96;
            long item = sm.ei.item[row];
            const float* src = (part == 0)
                ? &pre_text[item * 384 + c4 * 4]
                : &pre_visual[item * 768 + (part - 1) * KPART + c4 * 4];
            *(float4*)&sm.ei.sA[row * KPART + c4 * 4] = *(const float4*)src;
        }
        __syncthreads();

        const float* sa = sm.ei.sA + warp * KPART;
        const float* wp = g_Wc + (long)part * KPART * DIM + 4 * lane;

        u64 aa = 0, ab = 0;
        #pragma unroll 8
        for (int kk = 0; kk < KPART; ++kk) {
            ulonglong2 w2 = *(const ulonglong2*)(wp + (long)kk * DIM);
            u64 p0 = pk2(sa[kk]);
            ffma2(aa, p0, w2.x);
            ffma2(ab, p0, w2.y);
        }

        int row = row0 + warp;
        float2 fa = up2(aa), fb = up2(ab);
        float4 o;
        o.x = fa.x; o.y = fa.y; o.z = fb.x; o.w = fb.y;
        if (part == 0) {
            long item = sm.ei.item[warp];
            float4 ip = *(const float4*)&item_prompt[item * DIM + 4 * lane];
            float4 cb = *(const float4*)&g_cbias[4 * lane];
            o.x += ip.x - cb.x;
            o.y += ip.y - cb.y;
            o.z += ip.z - cb.z;
            o.w += ip.w - cb.w;
        }
        *(float4*)&g_part[part][row * DIM + 4 * lane] = o;
    }
}

// ---------------- f1 = relu(feat @ W1.T + b1), sums e_i partials in staging ----------------
// 16 rows/block, 512 threads, warp = 1 row, lane = 4 dims, K = 256
__global__ void __launch_bounds__(512) k_f1(const float* __restrict__ b1) {
    __shared__ __align__(16) float sA[16 * 256];       // 16 KB
    __shared__ float s_out[16][128];                   // 8 KB
    int tid = threadIdx.x;
    int warp = tid >> 5, lane = tid & 31;
    int row0 = blockIdx.x * 16;

    #pragma unroll
    for (int j = 0; j < 2; ++j) {
        int f4 = tid + j * 512;            // 0..1023
        int row = f4 >> 6, c4 = f4 & 63;
        float4 v;
        if (c4 < 32) {
            v = *(const float4*)&g_huf[(row0 + row) * DIM + c4 * 4];
        } else {
            int off = (row0 + row) * DIM + (c4 - 32) * 4;
            v = *(const float4*)&g_part[0][off];
            #pragma unroll
            for (int p = 1; p < NPART; ++p) {
                float4 t = *(const float4*)&g_part[p][off];
                v.x += t.x; v.y += t.y; v.z += t.z; v.w += t.w;
            }
        }
        *(float4*)&sA[row * 256 + c4 * 4] = v;
    }
    __syncthreads();

    const float* sa = sA + warp * 256;
    const float* wp = g_W1T + 4 * lane;

    u64 aa = 0, ab = 0;
    #pragma unroll 8
    for (int kk = 0; kk < 256; ++kk) {
        ulonglong2 w2 = *(const ulonglong2*)(wp + (long)kk * DIM);
        u64 p0 = pk2(sa[kk]);
        ffma2(aa, p0, w2.x);
        ffma2(ab, p0, w2.y);
    }

    float4 bb = *(const float4*)&b1[4 * lane];
    int row = row0 + warp;
    float2 fa = up2(aa), fb = up2(ab);
    float4 o;
    o.x = fmaxf(fa.x + bb.x, 0.f);
    o.y = fmaxf(fa.y + bb.y, 0.f);
    o.z = fmaxf(fb.x + bb.z, 0.f);
    o.w = fmaxf(fb.y + bb.w, 0.f);
    *(float4*)&g_f1[row * DIM + 4 * lane] = o;
    *(float4*)&s_out[warp][4 * lane] = o;
    __syncthreads();

    if (tid < 128) {
        float s = 0.f, q = 0.f;
        #pragma unroll
        for (int r = 0; r < 16; ++r) {
            float x = s_out[r][tid];
            s += x;
            q = fmaf(x, x, q);
        }
        g_p1s[blockIdx.x * 128 + tid] = s;
        g_p1q[blockIdx.x * 128 + tid] = q;
    }
}

// ---------------- fold BN1 into W2 ----------------
__global__ void k_mid(const float* __restrict__ g1, const float* __restrict__ be1,
                      const float* __restrict__ W2, const float* __restrict__ b2) {
    __shared__ float sc[128], sh[128];
    int tid = threadIdx.x;
    float s = 0.f, q = 0.f;
    for (int i = 0; i < 256; ++i) {
        s += g_p1s[i * 128 + tid];
        q += g_p1q[i * 128 + tid];
    }
    float mean = s * (1.0f / (float)B_SZ);
    float var = q * (1.0f / (float)B_SZ) - mean * mean;
    float rstd = rsqrtf(var + 1e-5f);
    float scale = g1[tid] * rstd;
    sc[tid] = scale;
    sh[tid] = be1[tid] - mean * scale;
    __syncthreads();
    if (tid < 64) {
        int d = tid;
        float bacc = 0.f;
        for (int k = 0; k < 128; ++k) {
            float w = W2[d * 128 + k];
            g_effW2T[k * 64 + d] = w * sc[k];
            bacc = fmaf(w, sh[k], bacc);
        }
        g_effb2[d] = b2[d] + bacc;
    }
}

// ---------------- f2 = relu(f1 @ effW2T + effb2) ----------------
// 16 rows/block, 512 threads, warp = 1 row, lane = 2 dims, K = 128
__global__ void __launch_bounds__(512) k_f2() {
    __shared__ __align__(16) float sA[16 * 128];   // 8 KB
    __shared__ float s_out[16][64];                // 4 KB
    int tid = threadIdx.x;
    int warp = tid >> 5, lane = tid & 31;
    int row0 = blockIdx.x * 16;

    {
        int f4 = tid;                       // 0..511
        int row = f4 >> 5, c4 = f4 & 31;
        *(float4*)&sA[row * 128 + c4 * 4] =
            *(const float4*)&g_f1[(row0 + row) * DIM + c4 * 4];
    }
    __syncthreads();

    const float* sa = sA + warp * 128;
    const float* wp = g_effW2T + 2 * lane;

    u64 a = 0;
    #pragma unroll 8
    for (int kk = 0; kk < 128; ++kk) {
        u64 w2 = *(const u64*)(wp + kk * 64);
        u64 p0 = pk2(sa[kk]);
        ffma2(a, p0, w2);
    }

    float2 bb = *(const float2*)&g_effb2[2 * lane];
    int row = row0 + warp;
    float2 fa = up2(a);
    float2 o;
    o.x = fmaxf(fa.x + bb.x, 0.f);
    o.y = fmaxf(fa.y + bb.y, 0.f);
    *(float2*)&g_f2[row * 64 + 2 * lane] = o;
    *(float2*)&s_out[warp][2 * lane] = o;
    __syncthreads();

    if (tid < 64) {
        float s = 0.f, q = 0.f;
        #pragma unroll
        for (int r = 0; r < 16; ++r) {
            float x = s_out[r][tid];
            s += x;
            q = fmaf(x, x, q);
        }
        g_p2s[blockIdx.x * 64 + tid] = s;
        g_p2q[blockIdx.x * 64 + tid] = q;
    }
}

// ---------------- fold BN2 into Wp ----------------
__global__ void k_mid2(const float* __restrict__ g2, const float* __restrict__ be2,
                       const float* __restrict__ Wp, const float* __restrict__ bp) {
    __shared__ float contrib[64];
    int tid = threadIdx.x;  // 64
    float s = 0.f, q = 0.f;
    for (int i = 0; i < 256; ++i) {
        s += g_p2s[i * 64 + tid];
        q += g_p2q[i * 64 + tid];
    }
    float mean = s * (1.0f / (float)B_SZ);
    float var = q * (1.0f / (float)B_SZ) - mean * mean;
    float rstd = rsqrtf(var + 1e-5f);
    float scale = g2[tid] * rstd;
    float shift = be2[tid] - mean * scale;
    float w = Wp[tid];
    g_effWp[tid] = w * scale;
    contrib[tid] = w * shift;
    __syncthreads();
    if (tid == 0) {
        float acc = bp[0];
        for (int i = 0; i < 64; ++i) acc += contrib[i];
        g_effbp = acc;
    }
}

// ---------------- pred ----------------
__global__ void k_pred(float* __restrict__ out_pred) {
    int tid = threadIdx.x;
    int lane = tid & 31;
    int row = blockIdx.x * 8 + (tid >> 5);
    float a = g_f2[row * 64 + lane] * g_effWp[lane]
            + g_f2[row * 64 + 32 + lane] * g_effWp[32 + lane];
    #pragma unroll
    for (int o = 16; o > 0; o >>= 1) a += __shfl_down_sync(0xffffffffu, a, o);
    if (lane == 0) {
        float x = a + g_effbp;
        out_pred[row] = 1.0f / (1.0f + expf(-x));
    }
}

// ---------------- launcher ----------------
extern "C" void kernel_launch(void* const* d_in, const int* in_sizes, int n_in,
                              void* d_out, int out_size) {
    const int*   nodes_u       = (const int*)d_in[0];
    const int*   nodes_v       = (const int*)d_in[1];
    const int*   nodes_d       = (const int*)d_in[2];
    const int*   inter_items   = (const int*)d_in[3];
    const int*   top_n         = (const int*)d_in[4];
    const float* prototypes    = (const float*)d_in[5];
    const float* pre_text      = (const float*)d_in[6];
    const float* pre_visual    = (const float*)d_in[7];
    const float* Wt            = (const float*)d_in[8];
    const float* bt            = (const float*)d_in[9];
    const float* Wv            = (const float*)d_in[10];
    const float* bv            = (const float*)d_in[11];
    const float* user_prompt   = (const float*)d_in[12];
    const float* item_prompt   = (const float*)d_in[13];
    const float* domain_prompt = (const float*)d_in[14];
    const float* W1            = (const float*)d_in[15];
    const float* b1            = (const float*)d_in[16];
    const float* g1            = (const float*)d_in[17];
    const float* be1           = (const float*)d_in[18];
    const float* W2            = (const float*)d_in[19];
    const float* b2            = (const float*)d_in[20];
    const float* g2            = (const float*)d_in[21];
    const float* be2           = (const float*)d_in[22];
    const float* Wp            = (const float*)d_in[23];
    const float* bp            = (const float*)d_in[24];

    float* out      = (float*)d_out;
    float* out_pred = out;
    float* out_pu   = out + B_SZ;
    float* out_hu   = out + B_SZ + B_SZ * DIM;
    float* out_pd   = out + B_SZ + 2 * B_SZ * DIM;

    k_prep<<<832, 256>>>(Wt, Wv, W1, bt, bv);
    k_main<<<256 + 256 * NPART, 512>>>(nodes_u, nodes_d, inter_items, top_n,
                                       prototypes, user_prompt, domain_prompt,
                                       nodes_v, pre_text, pre_visual, item_prompt,
                                       out_pu, out_hu, out_pd);
    k_f1<<<B_SZ / 16, 512>>>(b1);
    k_mid<<<1, 128>>>(g1, be1, W2, b2);
    k_f2<<<B_SZ / 16, 512>>>();
    k_mid2<<<1, 64>>>(g2, be2, Wp, bp);
    k_pred<<<B_SZ / 8, 256>>>(out_pred);
}